// round 1
// baseline (speedup 1.0000x reference)
#include <cuda_runtime.h>
#include <cstdint>

#define BN 32
#define AN 8400
#define CN 80
#define MN 64
#define TK 13
#define TILE 128
#define NT 66            // ceil(8400/128)
#define EPSF 1e-9f
#define SMEM1 ((TILE*81 + MN*129)*4)

// ---------------- scratch (device globals; no allocation) ----------------
__device__ float d_cand_v[BN*MN*NT*TK];
__device__ int   d_cand_i[BN*MN*NT*TK];
__device__ int   d_sel[BN*MN*TK];
__device__ int   d_cnt[BN*AN];
__device__ int   d_msum[BN*AN];
__device__ float d_maxmet[BN*MN];
__device__ float d_maxiou[BN*MN];
__device__ int   d_ma[BN*AN];
__device__ float d_alignv[BN*AN];
__device__ float d_scale[BN*AN];
__device__ int   d_colv[BN*AN];

// ---------------- init ----------------
__global__ void k_init() {
    int idx = blockIdx.x*blockDim.x + threadIdx.x;
    if (idx < BN*AN) { d_cnt[idx] = 0; d_msum[idx] = 0; }
    if (idx < BN*MN) { d_maxmet[idx] = 0.f; d_maxiou[idx] = 0.f; }
}

// ---------------- stage 1: tiled metrics + per-tile top-13 ----------------
extern __shared__ float smem_dyn[];

__global__ void k_stage1(const float* __restrict__ ps, const float* __restrict__ pb,
                         const float* __restrict__ ap, const int* __restrict__ gl,
                         const float* __restrict__ gb)
{
    float* sc  = smem_dyn;             // [128][81] score tile (pitch 81: conflict-free gathers)
    float* met = smem_dyn + TILE*81;   // [64][129] metric tile (pitch 129: conflict-free rows)
    __shared__ float s_gx1[MN], s_gy1[MN], s_gx2[MN], s_gy2[MN], s_gar[MN];
    __shared__ int   s_lab[MN];

    const int b = blockIdx.y;
    const int tile = blockIdx.x;
    const int tid = threadIdx.x;
    const int abase = tile * TILE;

    if (tid < MN) {
        float4 g = reinterpret_cast<const float4*>(gb)[b*MN + tid];
        s_gx1[tid] = g.x; s_gy1[tid] = g.y; s_gx2[tid] = g.z; s_gy2[tid] = g.w;
        s_gar[tid] = fmaxf(g.z - g.x, 0.f) * fmaxf(g.w - g.y, 0.f);
        s_lab[tid] = gl[b*MN + tid];
    }
    // coalesced score tile load
    const float4* src = reinterpret_cast<const float4*>(ps + (size_t)(b*AN + abase)*CN);
    for (int i = tid; i < TILE*CN/4; i += TILE) {
        int flat = i*4; int r = flat/CN; int c = flat - r*CN;
        float4 v = make_float4(0.f,0.f,0.f,0.f);
        if (abase + r < AN) v = src[i];
        float* d = sc + r*81 + c;
        d[0]=v.x; d[1]=v.y; d[2]=v.z; d[3]=v.w;
    }
    __syncthreads();

    int a = abase + tid;
    bool valid = a < AN;
    float4 p = make_float4(0.f,0.f,0.f,0.f);
    float2 pt = make_float2(-1e9f,-1e9f);
    if (valid) {
        p  = reinterpret_cast<const float4*>(pb)[b*AN + a];
        pt = reinterpret_cast<const float2*>(ap)[a];
    }
    float parea = fmaxf(p.z - p.x, 0.f) * fmaxf(p.w - p.y, 0.f);

    #pragma unroll 4
    for (int m = 0; m < MN; m++) {
        float gx1 = s_gx1[m], gy1 = s_gy1[m], gx2 = s_gx2[m], gy2 = s_gy2[m];
        float ox = fminf(gx2, p.z) - fmaxf(gx1, p.x);
        float oy = fminf(gy2, p.w) - fmaxf(gy1, p.y);
        float ov = fmaxf(ox, 0.f) * fmaxf(oy, 0.f);
        float iou = ov / (s_gar[m] + parea - ov + EPSF);
        float dmin = fminf(fminf(pt.x - gx1, pt.y - gy1), fminf(gx2 - pt.x, gy2 - pt.y));
        float metr = 0.f;
        if (valid && dmin > EPSF) {
            float s = sc[tid*81 + s_lab[m]];
            float i2 = iou * iou;
            metr = s * (i2 * i2 * i2);   // score^1 * iou^6
        }
        met[m*129 + tid] = metr;
    }
    __syncthreads();

    if (tid < MN) {                      // thread-per-gt row reduction
        float tv[TK]; int ti[TK];
        #pragma unroll
        for (int k = 0; k < TK; k++) { tv[k] = 0.f; ti[k] = -1; }
        const float* row = met + tid*129;
        for (int i = 0; i < TILE; i++) {
            float v = row[i];
            if (v > tv[TK-1]) {          // stable: equal value keeps earlier index
                tv[TK-1] = v; ti[TK-1] = abase + i;
                #pragma unroll
                for (int k = TK-1; k > 0; --k) {
                    if (tv[k] > tv[k-1]) {
                        float x = tv[k]; tv[k] = tv[k-1]; tv[k-1] = x;
                        int   y = ti[k]; ti[k] = ti[k-1]; ti[k-1] = y;
                    }
                }
            }
        }
        int base = ((b*MN + tid)*NT + tile)*TK;
        #pragma unroll
        for (int k = 0; k < TK; k++) { d_cand_v[base+k] = tv[k]; d_cand_i[base+k] = ti[k]; }
    }
}

// ---------------- stage 2: per-(b,m) global top-13 merge ----------------
__global__ void k_stage2(const float* __restrict__ pad) {
    int bm = blockIdx.x*blockDim.x + threadIdx.x;
    if (bm >= BN*MN) return;
    int ob = bm*TK;
    if (pad[bm] < 0.5f) {
        #pragma unroll
        for (int k = 0; k < TK; k++) d_sel[ob+k] = -1;
        return;
    }
    float tv[TK]; int ti[TK];
    #pragma unroll
    for (int k = 0; k < TK; k++) { tv[k] = 0.f; ti[k] = -1; }
    int base = bm*NT*TK;
    for (int t = 0; t < NT; t++) {
        int tb = base + t*TK;
        #pragma unroll
        for (int k = 0; k < TK; k++) {
            float v = d_cand_v[tb+k];
            if (v <= tv[TK-1]) break;    // tile list sorted desc; ties keep earlier index
            int idx = d_cand_i[tb+k];
            tv[TK-1] = v; ti[TK-1] = idx;
            #pragma unroll
            for (int j = TK-1; j > 0; --j) {
                if (tv[j] > tv[j-1]) {
                    float x = tv[j]; tv[j] = tv[j-1]; tv[j-1] = x;
                    int   y = ti[j]; ti[j] = ti[j-1]; ti[j-1] = y;
                }
            }
        }
    }
    #pragma unroll
    for (int k = 0; k < TK; k++) d_sel[ob+k] = (tv[k] > 0.f) ? ti[k] : -1;
}

// ---------------- stage 3: sparse scatter of positives ----------------
__global__ void k_scatter() {
    int idx = blockIdx.x*blockDim.x + threadIdx.x;
    if (idx >= BN*MN*TK) return;
    int a = d_sel[idx];
    if (a < 0) return;
    int bm = idx / TK;
    int b = bm >> 6, m = bm & 63;
    atomicAdd(&d_cnt[b*AN + a], 1);
    atomicAdd(&d_msum[b*AN + a], m);
}

// ---------------- stage 4: per-anchor assignment ----------------
__global__ void k_assign(const float* __restrict__ ps, const float* __restrict__ pb,
                         const int* __restrict__ gl, const float* __restrict__ gb,
                         const int* __restrict__ bgp,
                         float* __restrict__ outL, float* __restrict__ outB)
{
    __shared__ float s_gx1[MN], s_gy1[MN], s_gx2[MN], s_gy2[MN], s_gar[MN];
    __shared__ int   s_lab[MN];
    int b = blockIdx.y;
    int tid = threadIdx.x;
    if (tid < MN) {
        float4 g = reinterpret_cast<const float4*>(gb)[b*MN + tid];
        s_gx1[tid] = g.x; s_gy1[tid] = g.y; s_gx2[tid] = g.z; s_gy2[tid] = g.w;
        s_gar[tid] = fmaxf(g.z - g.x, 0.f) * fmaxf(g.w - g.y, 0.f);
        s_lab[tid] = gl[b*MN + tid];
    }
    __syncthreads();
    int a = blockIdx.x*blockDim.x + tid;
    if (a >= AN) return;
    int idx = b*AN + a;
    int c = d_cnt[idx];
    float4 p = reinterpret_cast<const float4*>(pb)[idx];
    float parea = fmaxf(p.z - p.x, 0.f) * fmaxf(p.w - p.y, 0.f);

    int m_a;
    if (c == 0) m_a = -1;
    else if (c == 1) m_a = d_msum[idx];
    else {                                // multi-claimed: argmax IoU over ALL gts (incl padded)
        float best = -1.f; int bi2 = 0;
        for (int m = 0; m < MN; m++) {
            float ox = fminf(s_gx2[m], p.z) - fmaxf(s_gx1[m], p.x);
            float oy = fminf(s_gy2[m], p.w) - fmaxf(s_gy1[m], p.y);
            float ov = fmaxf(ox, 0.f) * fmaxf(oy, 0.f);
            float iou = ov / (s_gar[m] + parea - ov + EPSF);
            if (iou > best) { best = iou; bi2 = m; }   // first max (matches argmax)
        }
        m_a = bi2;
    }

    float alignv = 0.f;
    if (m_a >= 0) {
        float ox = fminf(s_gx2[m_a], p.z) - fmaxf(s_gx1[m_a], p.x);
        float oy = fminf(s_gy2[m_a], p.w) - fmaxf(s_gy1[m_a], p.y);
        float ov = fmaxf(ox, 0.f) * fmaxf(oy, 0.f);
        float iou = ov / (s_gar[m_a] + parea - ov + EPSF);
        float s = __ldg(ps + (size_t)idx*CN + s_lab[m_a]);
        float i2 = iou * iou;
        alignv = s * (i2 * i2 * i2);
        atomicMax((int*)&d_maxmet[b*MN + m_a], __float_as_int(alignv)); // non-negative floats
        atomicMax((int*)&d_maxiou[b*MN + m_a], __float_as_int(iou));
    }
    d_ma[idx] = m_a;
    d_alignv[idx] = alignv;

    int mm = (m_a >= 0) ? m_a : 0;       // background takes gt 0 (argmax of all-zero mask)
    int bgv = bgp ? *bgp : 80;
    outL[idx] = (m_a >= 0) ? (float)s_lab[m_a] : (float)bgv;
    reinterpret_cast<float4*>(outB)[idx] =
        make_float4(s_gx1[mm], s_gy1[mm], s_gx2[mm], s_gy2[mm]);
}

// ---------------- stage 5: per-anchor score scale (1 div/anchor) ----------------
__global__ void k_scale(const int* __restrict__ gl) {
    int idx = blockIdx.x*blockDim.x + threadIdx.x;
    if (idx >= BN*AN) return;
    int m_a = d_ma[idx];
    float sc = 0.f; int col = -1;
    if (m_a >= 0) {
        int b = idx / AN;
        int bm = b*MN + m_a;
        sc = d_alignv[idx] / (d_maxmet[bm] + EPSF) * d_maxiou[bm];
        col = gl[bm];
    }
    d_scale[idx] = sc; d_colv[idx] = col;
}

// ---------------- stage 6: vectorized score write (86 MB) ----------------
__global__ void k_scores(float* __restrict__ outS) {
    int idx = blockIdx.x*blockDim.x + threadIdx.x;   // over B*A*C/4 float4s
    if (idx >= BN*AN*CN/4) return;
    int a  = idx / (CN/4);
    int c0 = (idx - a*(CN/4))*4;
    int col = d_colv[a];
    float s = d_scale[a];
    float4 v;
    v.x = (c0   == col) ? s : 0.f;
    v.y = (c0+1 == col) ? s : 0.f;
    v.z = (c0+2 == col) ? s : 0.f;
    v.w = (c0+3 == col) ? s : 0.f;
    reinterpret_cast<float4*>(outS)[idx] = v;
}

// ---------------- launch ----------------
extern "C" void kernel_launch(void* const* d_in, const int* in_sizes, int n_in,
                              void* d_out, int out_size)
{
    const float* ps  = (const float*)d_in[0];   // pred_scores  (B,A,C)
    const float* pb  = (const float*)d_in[1];   // pred_bboxes  (B,A,4)
    const float* ap  = (const float*)d_in[2];   // anchor_points(A,2)
    const int*   gl  = (const int*)d_in[3];     // gt_labels    (B,M,1)
    const float* gb  = (const float*)d_in[4];   // gt_bboxes    (B,M,4)
    const float* pad = (const float*)d_in[5];   // pad_gt_mask  (B,M,1)
    const int*   bg  = (n_in >= 7) ? (const int*)d_in[6] : nullptr;

    float* outL = (float*)d_out;                       // labels  (B*A)
    float* outB = outL + (size_t)BN*AN;                // bboxes  (B*A*4)
    float* outS = outL + (size_t)BN*AN*5;              // scores  (B*A*C)

    cudaFuncSetAttribute(k_stage1, cudaFuncAttributeMaxDynamicSharedMemorySize, SMEM1);

    k_init   <<<(BN*AN + 255)/256, 256>>>();
    k_stage1 <<<dim3(NT, BN), TILE, SMEM1>>>(ps, pb, ap, gl, gb);
    k_stage2 <<<(BN*MN + 255)/256, 256>>>(pad);
    k_scatter<<<(BN*MN*TK + 255)/256, 256>>>();
    k_assign <<<dim3((AN + 255)/256, BN), 256>>>(ps, pb, gl, gb, bg, outL, outB);
    k_scale  <<<(BN*AN + 255)/256, 256>>>(gl);
    k_scores <<<(BN*AN*CN/4 + 255)/256, 256>>>(outS);
}

// round 7
// speedup vs baseline: 1.8021x; 1.8021x over previous
#include <cuda_runtime.h>
#include <cstdint>

#define BN 32
#define AN 8400
#define CN 80
#define MN 64
#define TK 13
#define TILE 256
#define NT 33            // ceil(8400/256)
#define EPSF 1e-9f
#define MPITCH 257       // met tile pitch (odd -> conflict-free column reads)
#define CPITCH 53        // in-block candidate pitch (odd)
#define SMEM1 (MN*MPITCH*4)

// ---------------- scratch (device globals; no allocation) ----------------
__device__ float d_cand_v[BN*MN*NT*TK];
__device__ int   d_cand_i[BN*MN*NT*TK];
__device__ int   d_cnt[BN*AN];
__device__ int   d_msum[BN*AN];
__device__ float d_maxmet[BN*MN];
__device__ float d_maxiou[BN*MN];
__device__ int   d_ma[BN*AN];
__device__ float d_alignv[BN*AN];

// ---------------- init ----------------
__global__ void k_init() {
    int idx = blockIdx.x*blockDim.x + threadIdx.x;
    if (idx < BN*AN) { d_cnt[idx] = 0; d_msum[idx] = 0; }
    if (idx < BN*MN) { d_maxmet[idx] = 0.f; d_maxiou[idx] = 0.f; }
}

// ---------------- stage 1: metrics + per-tile top-13 ----------------
extern __shared__ float smem_dyn[];

__global__ void __launch_bounds__(TILE, 2)
k_stage1(const float* __restrict__ ps, const float* __restrict__ pb,
         const float* __restrict__ ap, const int* __restrict__ gl,
         const float* __restrict__ gb)
{
    float* met = smem_dyn;                      // [64][257]
    __shared__ float4 s_gbox[MN];
    __shared__ float  s_gar[MN];
    __shared__ int    s_lab[MN];

    const int b = blockIdx.y;
    const int tile = blockIdx.x;
    const int tid = threadIdx.x;
    const int abase = tile * TILE;

    if (tid < MN) {
        float4 g = reinterpret_cast<const float4*>(gb)[b*MN + tid];
        s_gbox[tid] = g;
        s_gar[tid] = fmaxf(g.z - g.x, 0.f) * fmaxf(g.w - g.y, 0.f);
        s_lab[tid] = gl[b*MN + tid];
    }
    __syncthreads();

    const int a = abase + tid;
    const bool valid = a < AN;
    float4 p = make_float4(0.f,0.f,0.f,0.f);
    float2 pt = make_float2(-1e9f,-1e9f);
    if (valid) {
        p  = reinterpret_cast<const float4*>(pb)[b*AN + a];
        pt = reinterpret_cast<const float2*>(ap)[a];
    }
    const float parea = fmaxf(p.z - p.x, 0.f) * fmaxf(p.w - p.y, 0.f);
    const float* srow = ps + (size_t)(b*AN + a)*CN;

    #pragma unroll 4
    for (int m = 0; m < MN; m++) {
        float4 g = s_gbox[m];
        float ox = fminf(g.z, p.z) - fmaxf(g.x, p.x);
        float oy = fminf(g.w, p.w) - fmaxf(g.y, p.y);
        float ov = fmaxf(ox, 0.f) * fmaxf(oy, 0.f);
        float iou = __fdividef(ov, s_gar[m] + parea - ov + EPSF);
        float dmin = fminf(fminf(pt.x - g.x, pt.y - g.y), fminf(g.z - pt.x, g.w - pt.y));
        float metr = 0.f;
        if (valid && dmin > EPSF) {             // rare: gather only inside-gt
            float s = __ldg(srow + s_lab[m]);
            float i2 = iou * iou;
            metr = s * (i2 * i2 * i2);          // score^1 * iou^6
        }
        met[m*MPITCH + tid] = metr;
    }
    __syncthreads();

    // quarter scan: thread (q, m) scans 64 contiguous anchors of gt m
    const int q = tid >> 6;
    const int m = tid & 63;
    float tv[TK]; int ti[TK];
    #pragma unroll
    for (int k = 0; k < TK; k++) { tv[k] = 0.f; ti[k] = -1; }
    {
        const float* row = met + m*MPITCH + q*64;
        const int ibase = abase + q*64;
        for (int i = 0; i < 64; i++) {
            float v = row[i];
            if (v > tv[TK-1]) {                 // stable: ties keep earlier index
                tv[TK-1] = v; ti[TK-1] = ibase + i;
                #pragma unroll
                for (int k = TK-1; k > 0; --k) {
                    if (tv[k] > tv[k-1]) {
                        float x = tv[k]; tv[k] = tv[k-1]; tv[k-1] = x;
                        int   y = ti[k]; ti[k] = ti[k-1]; ti[k-1] = y;
                    }
                }
            }
        }
    }
    __syncthreads();                            // all met reads done

    // in-block 4-way merge (alias candidate buffers over met)
    float* cv = met;                            // [64][53]
    int*   ci = (int*)(met + MN*CPITCH);        // [64][53]
    {
        int base = m*CPITCH + q*TK;
        #pragma unroll
        for (int k = 0; k < TK; k++) { cv[base+k] = tv[k]; ci[base+k] = ti[k]; }
    }
    __syncthreads();

    if (tid < MN) {
        float mv[TK]; int mi[TK];
        #pragma unroll
        for (int k = 0; k < TK; k++) { mv[k] = 0.f; mi[k] = -1; }
        int rbase = tid*CPITCH;
        for (int qq = 0; qq < 4; qq++) {        // ascending q => ascending indices
            int lb = rbase + qq*TK;
            #pragma unroll
            for (int k = 0; k < TK; k++) {
                float v = cv[lb+k];
                if (v <= mv[TK-1]) break;       // list sorted desc
                int idx = ci[lb+k];
                mv[TK-1] = v; mi[TK-1] = idx;
                #pragma unroll
                for (int j = TK-1; j > 0; --j) {
                    if (mv[j] > mv[j-1]) {
                        float x = mv[j]; mv[j] = mv[j-1]; mv[j-1] = x;
                        int   y = mi[j]; mi[j] = mi[j-1]; mi[j-1] = y;
                    }
                }
            }
        }
        int gbase = ((b*MN + tid)*NT + tile)*TK;
        #pragma unroll
        for (int k = 0; k < TK; k++) { d_cand_v[gbase+k] = mv[k]; d_cand_i[gbase+k] = mi[k]; }
    }
}

// ---------------- stage 2: per-(b,m) global merge + scatter ----------------
__global__ void k_stage2(const float* __restrict__ pad) {
    int bm = blockIdx.x*blockDim.x + threadIdx.x;
    if (bm >= BN*MN) return;
    if (pad[bm] < 0.5f) return;                 // padded gt contributes nothing
    float tv[TK]; int ti[TK];
    #pragma unroll
    for (int k = 0; k < TK; k++) { tv[k] = 0.f; ti[k] = -1; }
    int base = bm*NT*TK;
    for (int t = 0; t < NT; t++) {
        int tb = base + t*TK;
        #pragma unroll
        for (int k = 0; k < TK; k++) {
            float v = d_cand_v[tb+k];
            if (v <= tv[TK-1]) break;
            int idx = d_cand_i[tb+k];
            tv[TK-1] = v; ti[TK-1] = idx;
            #pragma unroll
            for (int j = TK-1; j > 0; --j) {
                if (tv[j] > tv[j-1]) {
                    float x = tv[j]; tv[j] = tv[j-1]; tv[j-1] = x;
                    int   y = ti[j]; ti[j] = ti[j-1]; ti[j-1] = y;
                }
            }
        }
    }
    int b = bm >> 6, m = bm & 63;
    #pragma unroll
    for (int k = 0; k < TK; k++) {
        if (tv[k] > 0.f) {
            int a = ti[k];
            atomicAdd(&d_cnt[b*AN + a], 1);
            atomicAdd(&d_msum[b*AN + a], m);
        }
    }
}

// ---------------- stage 3: per-anchor assignment ----------------
__global__ void k_assign(const float* __restrict__ ps, const float* __restrict__ pb,
                         const int* __restrict__ gl, const float* __restrict__ gb,
                         const int* __restrict__ bgp,
                         float* __restrict__ outL, float* __restrict__ outB)
{
    __shared__ float4 s_gbox[MN];
    __shared__ float  s_gar[MN];
    __shared__ int    s_lab[MN];
    int b = blockIdx.y;
    int tid = threadIdx.x;
    if (tid < MN) {
        float4 g = reinterpret_cast<const float4*>(gb)[b*MN + tid];
        s_gbox[tid] = g;
        s_gar[tid] = fmaxf(g.z - g.x, 0.f) * fmaxf(g.w - g.y, 0.f);
        s_lab[tid] = gl[b*MN + tid];
    }
    __syncthreads();
    int a = blockIdx.x*blockDim.x + tid;
    if (a >= AN) return;
    int idx = b*AN + a;
    int c = d_cnt[idx];
    float4 p = reinterpret_cast<const float4*>(pb)[idx];
    float parea = fmaxf(p.z - p.x, 0.f) * fmaxf(p.w - p.y, 0.f);

    int m_a;
    if (c == 0) m_a = -1;
    else if (c == 1) m_a = d_msum[idx];
    else {                                      // argmax IoU over ALL gts (matches reference)
        float best = -1.f; int bi2 = 0;
        for (int m = 0; m < MN; m++) {
            float4 g = s_gbox[m];
            float ox = fminf(g.z, p.z) - fmaxf(g.x, p.x);
            float oy = fminf(g.w, p.w) - fmaxf(g.y, p.y);
            float ov = fmaxf(ox, 0.f) * fmaxf(oy, 0.f);
            float iou = __fdividef(ov, s_gar[m] + parea - ov + EPSF);
            if (iou > best) { best = iou; bi2 = m; }
        }
        m_a = bi2;
    }

    float alignv = 0.f;
    if (m_a >= 0) {
        float4 g = s_gbox[m_a];
        float ox = fminf(g.z, p.z) - fmaxf(g.x, p.x);
        float oy = fminf(g.w, p.w) - fmaxf(g.y, p.y);
        float ov = fmaxf(ox, 0.f) * fmaxf(oy, 0.f);
        float iou = __fdividef(ov, s_gar[m_a] + parea - ov + EPSF);
        float s = __ldg(ps + (size_t)idx*CN + s_lab[m_a]);
        float i2 = iou * iou;
        alignv = s * (i2 * i2 * i2);
        atomicMax((int*)&d_maxmet[b*MN + m_a], __float_as_int(alignv)); // values >= 0
        atomicMax((int*)&d_maxiou[b*MN + m_a], __float_as_int(iou));
    }
    d_ma[idx] = m_a;
    d_alignv[idx] = alignv;

    int mm = (m_a >= 0) ? m_a : 0;              // bg anchors take gt 0 box (argmax of zeros)
    int bgv = bgp ? *bgp : 80;
    outL[idx] = (m_a >= 0) ? (float)s_lab[m_a] : (float)bgv;
    float4 g = s_gbox[mm];
    reinterpret_cast<float4*>(outB)[idx] = g;
}

// ---------------- stage 4: fused scale + vectorized score write ----------------
__global__ void k_scores(const int* __restrict__ gl, float* __restrict__ outS) {
    int idx = blockIdx.x*blockDim.x + threadIdx.x;   // over B*A*C/4 float4s
    if (idx >= BN*AN*CN/4) return;
    int a  = idx / (CN/4);
    int c0 = (idx - a*(CN/4))*4;
    int m_a = d_ma[a];
    float s = 0.f; int col = -1;
    if (m_a >= 0) {
        int b = a / AN;
        int bm = b*MN + m_a;
        s = __fdividef(d_alignv[a], d_maxmet[bm] + EPSF) * d_maxiou[bm];
        col = gl[bm];
    }
    float4 v;
    v.x = (c0   == col) ? s : 0.f;
    v.y = (c0+1 == col) ? s : 0.f;
    v.z = (c0+2 == col) ? s : 0.f;
    v.w = (c0+3 == col) ? s : 0.f;
    reinterpret_cast<float4*>(outS)[idx] = v;
}

// ---------------- launch ----------------
extern "C" void kernel_launch(void* const* d_in, const int* in_sizes, int n_in,
                              void* d_out, int out_size)
{
    const float* ps  = (const float*)d_in[0];   // pred_scores  (B,A,C)
    const float* pb  = (const float*)d_in[1];   // pred_bboxes  (B,A,4)
    const float* ap  = (const float*)d_in[2];   // anchor_points(A,2)
    const int*   gl  = (const int*)d_in[3];     // gt_labels    (B,M,1)
    const float* gb  = (const float*)d_in[4];   // gt_bboxes    (B,M,4)
    const float* pad = (const float*)d_in[5];   // pad_gt_mask  (B,M,1)
    const int*   bg  = (n_in >= 7) ? (const int*)d_in[6] : nullptr;

    float* outL = (float*)d_out;                       // labels  (B*A)
    float* outB = outL + (size_t)BN*AN;                // bboxes  (B*A*4)
    float* outS = outL + (size_t)BN*AN*5;              // scores  (B*A*C)

    // idempotent, host-side, no allocation; no static guard (harness rule)
    cudaFuncSetAttribute(k_stage1, cudaFuncAttributeMaxDynamicSharedMemorySize, SMEM1);

    k_init   <<<(BN*AN + 255)/256, 256>>>();
    k_stage1 <<<dim3(NT, BN), TILE, SMEM1>>>(ps, pb, ap, gl, gb);
    k_stage2 <<<(BN*MN + 255)/256, 256>>>(pad);
    k_assign <<<dim3((AN + 255)/256, BN), 256>>>(ps, pb, gl, gb, bg, outL, outB);
    k_scores <<<(BN*AN*CN/4 + 255)/256, 256>>>(gl, outS);
}